// round 12
// baseline (speedup 1.0000x reference)
#include <cuda_runtime.h>
#include <cuda_bf16.h>
#include <cstdint>

#define LDIM 1024   // h*w
#define CDIM 256
#define BATCH 8

// Scratch (no cudaMalloc allowed)
__device__ float g_qkv[BATCH * 3 * CDIM * LDIM];   // [b][768][l]
__device__ float g_attn[BATCH * LDIM * CDIM];      // [b][l][c]
__device__ float g_xt[BATCH * LDIM * CDIM];        // [b][l][c]
__device__ __nv_bfloat16 g_ktb[BATCH * 8 * LDIM * 32];  // [bh][j][d] bf16
__device__ __nv_bfloat16 g_vtb[BATCH * 8 * 32 * LDIM];  // [bh][d][j] bf16

// ---------- helpers ----------
__device__ __forceinline__ float ex2(float x) {
    float r; asm("ex2.approx.f32 %0, %1;" : "=f"(r) : "f"(x)); return r;
}
__device__ __forceinline__ void cp16(uint32_t smem, const void* gmem) {
    asm volatile("cp.async.ca.shared.global [%0], [%1], 16;" :: "r"(smem), "l"(gmem));
}
__device__ __forceinline__ void cp_commit() { asm volatile("cp.async.commit_group;"); }
template<int N> __device__ __forceinline__ void cp_wait() {
    asm volatile("cp.async.wait_group %0;" :: "n"(N));
}
__device__ __forceinline__ uint32_t s2u(const void* p) {
    uint32_t a;
    asm("{ .reg .u64 t; cvta.to.shared.u64 t, %1; cvt.u32.u64 %0, t; }" : "=r"(a) : "l"(p));
    return a;
}
__device__ __forceinline__ void ldsm4(uint32_t& r0, uint32_t& r1, uint32_t& r2, uint32_t& r3,
                                      uint32_t addr) {
    asm volatile("ldmatrix.sync.aligned.m8n8.x4.shared.b16 {%0,%1,%2,%3}, [%4];"
                 : "=r"(r0), "=r"(r1), "=r"(r2), "=r"(r3) : "r"(addr));
}
// pack two f32 -> bf16x2 {lo, hi}
__device__ __forceinline__ uint32_t bf2(float lo, float hi) {
    uint32_t r; asm("cvt.rn.bf16x2.f32 %0, %1, %2;" : "=r"(r) : "f"(hi), "f"(lo)); return r;
}

// ---------- mma.sync tf32 m16n8k8 (GEMMs) ----------
__device__ __forceinline__ void mma_tf32(float* d, const uint32_t* a, const uint32_t* b) {
    asm volatile(
        "mma.sync.aligned.m16n8k8.row.col.f32.tf32.tf32.f32 "
        "{%0,%1,%2,%3}, {%4,%5,%6,%7}, {%8,%9}, {%0,%1,%2,%3};"
        : "+f"(d[0]), "+f"(d[1]), "+f"(d[2]), "+f"(d[3])
        : "r"(a[0]), "r"(a[1]), "r"(a[2]), "r"(a[3]), "r"(b[0]), "r"(b[1]));
}
// ---------- mma.sync bf16 m16n8k16 (attention) ----------
__device__ __forceinline__ void mma_bf16(float* d, const uint32_t* a, const uint32_t* b) {
    asm volatile(
        "mma.sync.aligned.m16n8k16.row.col.f32.bf16.bf16.f32 "
        "{%0,%1,%2,%3}, {%4,%5,%6,%7}, {%8,%9}, {%0,%1,%2,%3};"
        : "+f"(d[0]), "+f"(d[1]), "+f"(d[2]), "+f"(d[3])
        : "r"(a[0]), "r"(a[1]), "r"(a[2]), "r"(a[3]), "r"(b[0]), "r"(b[1]));
}

// ---------------------------------------------------------------------------
// Transpose: x[b][c][l] -> xt[b][l][c]
// ---------------------------------------------------------------------------
__global__ __launch_bounds__(256)
void transpose_cl(const float* __restrict__ x, float* __restrict__ xt)
{
    __shared__ float tile[32][33];
    const int b  = blockIdx.z;
    const int c0 = blockIdx.y * 32;
    const int l0 = blockIdx.x * 32;
    const int tx = threadIdx.x, ty = threadIdx.y;
    const float* xb  = x  + (size_t)b * CDIM * LDIM;
    float*       xtb = xt + (size_t)b * LDIM * CDIM;
#pragma unroll
    for (int r = 0; r < 32; r += 8)
        tile[ty + r][tx] = xb[(size_t)(c0 + ty + r) * LDIM + l0 + tx];
    __syncthreads();
#pragma unroll
    for (int r = 0; r < 32; r += 8)
        xtb[(size_t)(l0 + ty + r) * CDIM + c0 + tx] = tile[tx][ty + r];
}

// ---------------------------------------------------------------------------
// K transpose + bf16 cast: K slice [d=32][l] per (b,h) -> ktb[bh][j][d]
// ---------------------------------------------------------------------------
__global__ __launch_bounds__(256)
void transpose_k(const float* __restrict__ qkv, __nv_bfloat16* __restrict__ kt)
{
    __shared__ float tile[32][33];
    const int bh = blockIdx.y;
    const int b  = bh >> 3, h = bh & 7;
    const int l0 = blockIdx.x * 32;
    const int tx = threadIdx.x, ty = threadIdx.y;
    const float* Kp  = qkv + (size_t)(b * 768 + 256 + h * 32) * LDIM;
    __nv_bfloat16* out = kt + (size_t)bh * LDIM * 32 + (size_t)l0 * 32;
#pragma unroll
    for (int r = 0; r < 32; r += 8)
        tile[ty + r][tx] = Kp[(size_t)(ty + r) * LDIM + l0 + tx];
    __syncthreads();
#pragma unroll
    for (int r = 0; r < 32; r += 8)
        out[(size_t)(ty + r) * 32 + tx] = __float2bfloat16(tile[tx][ty + r]);
}

// ---------------------------------------------------------------------------
// V cast: V slice [d=32][l] per (b,h) -> vtb[bh][d][j] bf16
// ---------------------------------------------------------------------------
__global__ __launch_bounds__(256)
void convert_v(const float* __restrict__ qkv, __nv_bfloat16* __restrict__ vt)
{
    const int bh = blockIdx.y;
    const int b  = bh >> 3, h = bh & 7;
    const float* Vp = qkv + (size_t)(b * 768 + 512 + h * 32) * LDIM;
    __nv_bfloat16* out = vt + (size_t)bh * 32 * LDIM;
    const int idx = (blockIdx.x * 256 + threadIdx.x) * 2;   // grid.x = 64
    float2 v = *(const float2*)&Vp[idx];
    *(uint32_t*)&out[idx] = bf2(v.x, v.y);
}

// ---------------------------------------------------------------------------
// tf32 mma.sync GEMM (unchanged — validated rounds 8-11)
// ---------------------------------------------------------------------------
#define APITCH 36
template<bool RES>
__global__ __launch_bounds__(256)
void gemm_mma(const float* __restrict__ W, const float* __restrict__ Bm,
              const float* __restrict__ bias, const float* __restrict__ resid,
              float* __restrict__ out, int M)
{
    extern __shared__ float sm[];
    float (*As)[128][APITCH] = (float(*)[128][APITCH])sm;
    float (*Bs)[128][APITCH] = (float(*)[128][APITCH])(sm + 2 * 128 * APITCH);

    const int b    = blockIdx.z;
    const int o0   = blockIdx.y * 128;
    const int l0   = blockIdx.x * 128;
    const int t    = threadIdx.x;
    const int wid  = t >> 5, lane = t & 31;
    const int wm   = (wid & 1) * 64;
    const int wn   = (wid >> 1) * 32;
    const int lr   = lane >> 2;
    const int lc   = lane & 3;

    const float* Wp = W  + (size_t)o0 * CDIM;
    const float* Bp = Bm + (size_t)b * LDIM * CDIM + (size_t)l0 * CDIM;

    const uint32_t asm_b = s2u(sm);
    const uint32_t bsm_b = asm_b + 2u * 128u * APITCH * 4u;

    auto load_chunk = [&](int c, int st) {
        const uint32_t stoff = (uint32_t)st * 128u * APITCH * 4u;
#pragma unroll
        for (int r = 0; r < 4; ++r) {
            const int idx = r * 256 + t;
            const int row = idx >> 3;
            const int c4  = (idx & 7) * 4;
            const uint32_t so = stoff + (uint32_t)(row * APITCH + c4) * 4u;
            cp16(asm_b + so, Wp + (size_t)row * CDIM + c * 32 + c4);
            cp16(bsm_b + so, Bp + (size_t)row * CDIM + c * 32 + c4);
        }
    };

    float acc[4][4][4];
#pragma unroll
    for (int i = 0; i < 4; ++i)
#pragma unroll
        for (int j = 0; j < 4; ++j)
#pragma unroll
            for (int k = 0; k < 4; ++k) acc[i][j][k] = 0.f;

    load_chunk(0, 0);
    cp_commit();

    for (int c = 0; c < 8; ++c) {
        if (c + 1 < 8) load_chunk(c + 1, (c + 1) & 1);
        cp_commit();
        cp_wait<1>();
        __syncthreads();
        const int st = c & 1;

#pragma unroll
        for (int ks = 0; ks < 4; ++ks) {
            const int kc = ks * 8 + lc;
            uint32_t af[4][4];
#pragma unroll
            for (int mf = 0; mf < 4; ++mf) {
                const int r0 = wm + mf * 16 + lr;
                af[mf][0] = __float_as_uint(As[st][r0][kc]);
                af[mf][1] = __float_as_uint(As[st][r0 + 8][kc]);
                af[mf][2] = __float_as_uint(As[st][r0][kc + 4]);
                af[mf][3] = __float_as_uint(As[st][r0 + 8][kc + 4]);
            }
            uint32_t bf[4][2];
#pragma unroll
            for (int nf = 0; nf < 4; ++nf) {
                const int n = wn + nf * 8 + lr;
                bf[nf][0] = __float_as_uint(Bs[st][n][kc]);
                bf[nf][1] = __float_as_uint(Bs[st][n][kc + 4]);
            }
#pragma unroll
            for (int mf = 0; mf < 4; ++mf)
#pragma unroll
                for (int nf = 0; nf < 4; ++nf)
                    mma_tf32(acc[mf][nf], af[mf], bf[nf]);
        }
        __syncthreads();
    }

#pragma unroll
    for (int mf = 0; mf < 4; ++mf) {
        const int r0 = o0 + wm + mf * 16 + lr;
        const float b0 = __ldg(&bias[r0]);
        const float b1 = __ldg(&bias[r0 + 8]);
        const size_t ro0 = ((size_t)b * M + r0) * LDIM;
        const size_t ro1 = ((size_t)b * M + r0 + 8) * LDIM;
#pragma unroll
        for (int nf = 0; nf < 4; ++nf) {
            const int cc = l0 + wn + nf * 8 + 2 * lc;
            float2 v0 = make_float2(acc[mf][nf][0] + b0, acc[mf][nf][1] + b0);
            float2 v1 = make_float2(acc[mf][nf][2] + b1, acc[mf][nf][3] + b1);
            if (RES) {
                float2 x0 = *(const float2*)&resid[ro0 + cc];
                float2 x1 = *(const float2*)&resid[ro1 + cc];
                v0.x += x0.x; v0.y += x0.y; v1.x += x1.x; v1.y += x1.y;
            }
            *(float2*)&out[ro0 + cc] = v0;
            *(float2*)&out[ro1 + cc] = v1;
        }
    }
}

// ---------------------------------------------------------------------------
// Flash attention v3: bf16 m16n8k16. Warp owns 32 query rows; key tile 32.
// K bf16 [j][d], V bf16 [d][j], P bf16 staged per-warp — all ldmatrix-native.
// Per iter: 12 ldsm.x4 + 32 k16-MMAs (vs 40 ldsm + 64 k8-MMAs in tf32 ver).
// Pitch 40 bf16 (80B rows): ldsm row banks = 20r mod 32 (permutation) and
// P-STS banks = 20lr+4nf+lc mod 32 (all distinct) -> conflict-free.
// ---------------------------------------------------------------------------
#define TPB 40
__global__ __launch_bounds__(64, 7)
void attn_mma(const float* __restrict__ qkv, const __nv_bfloat16* __restrict__ kt,
              const __nv_bfloat16* __restrict__ vt, float* __restrict__ attnout)
{
    __shared__ __align__(16) __nv_bfloat16 KS[2][32][TPB];   // [st][j][d]
    __shared__ __align__(16) __nv_bfloat16 VS[2][32][TPB];   // [st][d][j]
    __shared__ __align__(16) __nv_bfloat16 PSm[2][32][TPB];  // [warp][i][j]

    const int bh   = blockIdx.x;
    const int b    = bh >> 3;
    const int h    = bh & 7;
    const int qt   = blockIdx.y;
    const int t    = threadIdx.x;
    const int wid  = t >> 5, lane = t & 31;
    const int lr   = lane >> 2;   // 0..7
    const int lc   = lane & 3;    // 0..3
    const int mi   = lane >> 3;   // ldsm matrix index 0..3
    const int mr   = lane & 7;    // ldsm row within matrix

    const float* Qp = qkv + (size_t)(b * 768 + h * 32) * LDIM;
    const __nv_bfloat16* Ktp = kt + (size_t)bh * LDIM * 32;
    const __nv_bfloat16* Vtp = vt + (size_t)bh * 32 * LDIM;

    const float S = 0.17677669529663687f * 1.4426950408889634f;

    const int i0 = qt * 64 + wid * 32;

    // Q fragments bf16, persistent: qf[rh][kstep][4]
    uint32_t qf[2][2][4];
#pragma unroll
    for (int rh = 0; rh < 2; ++rh) {
        const int iq = i0 + rh * 16;
#pragma unroll
        for (int ks = 0; ks < 2; ++ks) {
            const int d0 = 16 * ks + 2 * lc;
            const float qa = Qp[(size_t)d0 * LDIM + iq + lr] * S;
            const float qb = Qp[(size_t)(d0 + 1) * LDIM + iq + lr] * S;
            const float qc = Qp[(size_t)d0 * LDIM + iq + lr + 8] * S;
            const float qd = Qp[(size_t)(d0 + 1) * LDIM + iq + lr + 8] * S;
            const float qe = Qp[(size_t)(d0 + 8) * LDIM + iq + lr] * S;
            const float qg = Qp[(size_t)(d0 + 9) * LDIM + iq + lr] * S;
            const float qh = Qp[(size_t)(d0 + 8) * LDIM + iq + lr + 8] * S;
            const float qi = Qp[(size_t)(d0 + 9) * LDIM + iq + lr + 8] * S;
            qf[rh][ks][0] = bf2(qa, qb);
            qf[rh][ks][1] = bf2(qc, qd);
            qf[rh][ks][2] = bf2(qe, qg);
            qf[rh][ks][3] = bf2(qh, qi);
        }
    }

    float o[2][4][4];
#pragma unroll
    for (int rh = 0; rh < 2; ++rh)
#pragma unroll
        for (int i = 0; i < 4; ++i)
#pragma unroll
            for (int j = 0; j < 4; ++j) o[rh][i][j] = 0.f;
    float rsA[2] = {0.f, 0.f}, rsB[2] = {0.f, 0.f};

    const uint32_t ks_u[2] = { s2u(&KS[0][0][0]), s2u(&KS[1][0][0]) };
    const uint32_t vs_u[2] = { s2u(&VS[0][0][0]), s2u(&VS[1][0][0]) };
    const uint32_t ps_u    = s2u(&PSm[wid][0][0]);

    // tile copier: K 32x32 + V 32x32 bf16; 64B data rows = 4x16B chunks
    auto copy_tile = [&](int st, int j0) {
#pragma unroll
        for (int r = 0; r < 2; ++r) {
            const int idx = r * 64 + t;          // 0..127
            const int row = idx >> 2;            // 0..31
            const int ch  = (idx & 3) * 8;       // bf16 elems: 0,8,16,24
            cp16(ks_u[st] + (uint32_t)(row * TPB + ch) * 2u,
                 Ktp + (size_t)(j0 + row) * 32 + ch);
            cp16(vs_u[st] + (uint32_t)(row * TPB + ch) * 2u,
                 Vtp + (size_t)row * LDIM + j0 + ch);
        }
    };

    copy_tile(0, 0);
    cp_commit();

    for (int jt = 0; jt < 32; ++jt) {
        const int st = jt & 1;
        if (jt < 31) copy_tile(st ^ 1, (jt + 1) * 32);
        cp_commit();
        cp_wait<1>();
        __syncthreads();

        // ---- QK: c[rh][g] over 32 keys; K B-frags shared across halves ----
        float c[2][4][4];
#pragma unroll
        for (int rh = 0; rh < 2; ++rh)
#pragma unroll
            for (int g = 0; g < 4; ++g)
#pragma unroll
                for (int k = 0; k < 4; ++k) c[rh][g][k] = 0.f;

#pragma unroll
        for (int g = 0; g < 4; ++g) {
            uint32_t r0, r1, r2, r3;
            ldsm4(r0, r1, r2, r3,
                  ks_u[st] + (uint32_t)(((g * 8 + mr) * TPB + mi * 8) * 2));
            uint32_t b01[2] = { r0, r1 }, b23[2] = { r2, r3 };
            mma_bf16(c[0][g], qf[0][0], b01);
            mma_bf16(c[0][g], qf[0][1], b23);
            mma_bf16(c[1][g], qf[1][0], b01);
            mma_bf16(c[1][g], qf[1][1], b23);
        }

        // ---- exp2 + row sums + stage P (bf16) ----
#pragma unroll
        for (int rh = 0; rh < 2; ++rh) {
#pragma unroll
            for (int g = 0; g < 4; ++g) {
                const float p0 = ex2(c[rh][g][0]), p1 = ex2(c[rh][g][1]);
                const float p2 = ex2(c[rh][g][2]), p3 = ex2(c[rh][g][3]);
                rsA[rh] += p0 + p1;
                rsB[rh] += p2 + p3;
                const int row0 = rh * 16 + lr;
                *(uint32_t*)&PSm[wid][row0][g * 8 + 2 * lc]     = bf2(p0, p1);
                *(uint32_t*)&PSm[wid][row0 + 8][g * 8 + 2 * lc] = bf2(p2, p3);
            }
        }
        __syncwarp();

        // ---- PV: o[rh][nf] += P * V ----
        uint32_t A[2][2][4];   // [rh][kstep]
#pragma unroll
        for (int rh = 0; rh < 2; ++rh)
#pragma unroll
            for (int kp = 0; kp < 2; ++kp)
                ldsm4(A[rh][kp][0], A[rh][kp][1], A[rh][kp][2], A[rh][kp][3],
                      ps_u + (uint32_t)(((rh * 16 + (mi & 1) * 8 + mr) * TPB
                                         + kp * 16 + (mi >> 1) * 8) * 2));
#pragma unroll
        for (int nf = 0; nf < 4; ++nf) {
            uint32_t v0, v1, v2, v3;
            ldsm4(v0, v1, v2, v3,
                  vs_u[st] + (uint32_t)(((nf * 8 + mr) * TPB + mi * 8) * 2));
            uint32_t b01[2] = { v0, v1 }, b23[2] = { v2, v3 };
            mma_bf16(o[0][nf], A[0][0], b01);
            mma_bf16(o[0][nf], A[0][1], b23);
            mma_bf16(o[1][nf], A[1][0], b01);
            mma_bf16(o[1][nf], A[1][1], b23);
        }
        __syncthreads();
    }

    // quad-reduce row sums, normalize, write [b][l][c]
#pragma unroll
    for (int rh = 0; rh < 2; ++rh) {
        float r0 = rsA[rh], r1 = rsB[rh];
        r0 += __shfl_xor_sync(0xFFFFFFFFu, r0, 1);
        r0 += __shfl_xor_sync(0xFFFFFFFFu, r0, 2);
        r1 += __shfl_xor_sync(0xFFFFFFFFu, r1, 1);
        r1 += __shfl_xor_sync(0xFFFFFFFFu, r1, 2);
        const float inv0 = 1.f / r0;
        const float inv1 = 1.f / r1;
        const int iq = i0 + rh * 16;
#pragma unroll
        for (int nf = 0; nf < 4; ++nf) {
            const int col = h * 32 + 8 * nf + 2 * lc;
            const size_t w0 = ((size_t)b * LDIM + iq + lr) * CDIM + col;
            const size_t w1 = ((size_t)b * LDIM + iq + lr + 8) * CDIM + col;
            *(float2*)&attnout[w0] = make_float2(o[rh][nf][0] * inv0, o[rh][nf][1] * inv0);
            *(float2*)&attnout[w1] = make_float2(o[rh][nf][2] * inv1, o[rh][nf][3] * inv1);
        }
    }
}

// ---------------------------------------------------------------------------
extern "C" void kernel_launch(void* const* d_in, const int* in_sizes, int n_in,
                              void* d_out, int out_size)
{
    const float* x      = (const float*)d_in[0];
    const float* w_qkv  = (const float*)d_in[1];
    const float* b_qkv  = (const float*)d_in[2];
    const float* w_proj = (const float*)d_in[3];
    const float* b_proj = (const float*)d_in[4];
    float* out = (float*)d_out;

    float *qkv = nullptr, *attn = nullptr, *xt = nullptr;
    __nv_bfloat16 *ktb = nullptr, *vtb = nullptr;
    cudaGetSymbolAddress((void**)&qkv, g_qkv);
    cudaGetSymbolAddress((void**)&attn, g_attn);
    cudaGetSymbolAddress((void**)&xt, g_xt);
    cudaGetSymbolAddress((void**)&ktb, g_ktb);
    cudaGetSymbolAddress((void**)&vtb, g_vtb);

    const int SMEMSZ = 4 * 128 * APITCH * 4;
    cudaFuncSetAttribute(gemm_mma<false>, cudaFuncAttributeMaxDynamicSharedMemorySize, SMEMSZ);
    cudaFuncSetAttribute(gemm_mma<true>,  cudaFuncAttributeMaxDynamicSharedMemorySize, SMEMSZ);

    // 1) transpose x -> xt[b][l][c]
    transpose_cl<<<dim3(LDIM / 32, CDIM / 32, BATCH), dim3(32, 8)>>>(x, xt);
    // 2) QKV GEMM (tf32 mma.sync): M=768, out [b][768][l]
    gemm_mma<false><<<dim3(LDIM / 128, 768 / 128, BATCH), 256, SMEMSZ>>>(w_qkv, xt, b_qkv, nullptr, qkv, 768);
    // 3) K transpose+cast -> ktb[bh][j][d]; V cast -> vtb[bh][d][j]
    transpose_k<<<dim3(LDIM / 32, BATCH * 8), dim3(32, 8)>>>(qkv, ktb);
    convert_v<<<dim3(64, BATCH * 8), 256>>>(qkv, vtb);
    // 4) flash attention v3 (bf16 m16n8k16 + ldmatrix)
    attn_mma<<<dim3(64, LDIM / 64), 64>>>(qkv, ktb, vtb, attn);
    // 5) proj GEMM (tf32) + bias + residual
    gemm_mma<true><<<dim3(LDIM / 128, 256 / 128, BATCH), 256, SMEMSZ>>>(w_proj, attn, b_proj, x, out, 256);
}

// round 14
// speedup vs baseline: 1.5595x; 1.5595x over previous
#include <cuda_runtime.h>
#include <cuda_bf16.h>
#include <cstdint>

#define LDIM 1024   // h*w
#define CDIM 256
#define BATCH 8

// Scratch (no cudaMalloc allowed)
__device__ float g_qkv[BATCH * 3 * CDIM * LDIM];   // [b][768][l]
__device__ float g_attn[BATCH * LDIM * CDIM];      // [b][l][c]
__device__ float g_xt[BATCH * LDIM * CDIM];        // [b][l][c]
__device__ __nv_bfloat16 g_ktb[BATCH * 8 * LDIM * 32];  // [bh][j][d] bf16
__device__ __nv_bfloat16 g_vtb[BATCH * 8 * 32 * LDIM];  // [bh][d][j] bf16

// ---------- helpers ----------
__device__ __forceinline__ float ex2(float x) {
    float r; asm("ex2.approx.f32 %0, %1;" : "=f"(r) : "f"(x)); return r;
}
__device__ __forceinline__ void cp16(uint32_t smem, const void* gmem) {
    asm volatile("cp.async.ca.shared.global [%0], [%1], 16;" :: "r"(smem), "l"(gmem));
}
__device__ __forceinline__ void cp_commit() { asm volatile("cp.async.commit_group;"); }
template<int N> __device__ __forceinline__ void cp_wait() {
    asm volatile("cp.async.wait_group %0;" :: "n"(N));
}
__device__ __forceinline__ uint32_t s2u(const void* p) {
    uint32_t a;
    asm("{ .reg .u64 t; cvta.to.shared.u64 t, %1; cvt.u32.u64 %0, t; }" : "=r"(a) : "l"(p));
    return a;
}
__device__ __forceinline__ void ldsm4(uint32_t& r0, uint32_t& r1, uint32_t& r2, uint32_t& r3,
                                      uint32_t addr) {
    asm volatile("ldmatrix.sync.aligned.m8n8.x4.shared.b16 {%0,%1,%2,%3}, [%4];"
                 : "=r"(r0), "=r"(r1), "=r"(r2), "=r"(r3) : "r"(addr));
}
// pack two f32 -> bf16x2 {lo, hi}
__device__ __forceinline__ uint32_t bf2(float lo, float hi) {
    uint32_t r; asm("cvt.rn.bf16x2.f32 %0, %1, %2;" : "=r"(r) : "f"(hi), "f"(lo)); return r;
}

// ---------- mma.sync tf32 m16n8k8 (GEMMs) ----------
__device__ __forceinline__ void mma_tf32(float* d, const uint32_t* a, const uint32_t* b) {
    asm volatile(
        "mma.sync.aligned.m16n8k8.row.col.f32.tf32.tf32.f32 "
        "{%0,%1,%2,%3}, {%4,%5,%6,%7}, {%8,%9}, {%0,%1,%2,%3};"
        : "+f"(d[0]), "+f"(d[1]), "+f"(d[2]), "+f"(d[3])
        : "r"(a[0]), "r"(a[1]), "r"(a[2]), "r"(a[3]), "r"(b[0]), "r"(b[1]));
}
// ---------- mma.sync bf16 m16n8k16 (attention) ----------
__device__ __forceinline__ void mma_bf16(float* d, const uint32_t* a, const uint32_t* b) {
    asm volatile(
        "mma.sync.aligned.m16n8k16.row.col.f32.bf16.bf16.f32 "
        "{%0,%1,%2,%3}, {%4,%5,%6,%7}, {%8,%9}, {%0,%1,%2,%3};"
        : "+f"(d[0]), "+f"(d[1]), "+f"(d[2]), "+f"(d[3])
        : "r"(a[0]), "r"(a[1]), "r"(a[2]), "r"(a[3]), "r"(b[0]), "r"(b[1]));
}

// ---------------------------------------------------------------------------
// Transpose: x[b][c][l] -> xt[b][l][c]
// ---------------------------------------------------------------------------
__global__ __launch_bounds__(256)
void transpose_cl(const float* __restrict__ x, float* __restrict__ xt)
{
    __shared__ float tile[32][33];
    const int b  = blockIdx.z;
    const int c0 = blockIdx.y * 32;
    const int l0 = blockIdx.x * 32;
    const int tx = threadIdx.x, ty = threadIdx.y;
    const float* xb  = x  + (size_t)b * CDIM * LDIM;
    float*       xtb = xt + (size_t)b * LDIM * CDIM;
#pragma unroll
    for (int r = 0; r < 32; r += 8)
        tile[ty + r][tx] = xb[(size_t)(c0 + ty + r) * LDIM + l0 + tx];
    __syncthreads();
#pragma unroll
    for (int r = 0; r < 32; r += 8)
        xtb[(size_t)(l0 + ty + r) * CDIM + c0 + tx] = tile[tx][ty + r];
}

// ---------------------------------------------------------------------------
// K transpose + bf16 cast: K slice [d=32][l] per (b,h) -> ktb[bh][j][d]
// ---------------------------------------------------------------------------
__global__ __launch_bounds__(256)
void transpose_k(const float* __restrict__ qkv, __nv_bfloat16* __restrict__ kt)
{
    __shared__ float tile[32][33];
    const int bh = blockIdx.y;
    const int b  = bh >> 3, h = bh & 7;
    const int l0 = blockIdx.x * 32;
    const int tx = threadIdx.x, ty = threadIdx.y;
    const float* Kp  = qkv + (size_t)(b * 768 + 256 + h * 32) * LDIM;
    __nv_bfloat16* out = kt + (size_t)bh * LDIM * 32 + (size_t)l0 * 32;
#pragma unroll
    for (int r = 0; r < 32; r += 8)
        tile[ty + r][tx] = Kp[(size_t)(ty + r) * LDIM + l0 + tx];
    __syncthreads();
#pragma unroll
    for (int r = 0; r < 32; r += 8)
        out[(size_t)(ty + r) * 32 + tx] = __float2bfloat16(tile[tx][ty + r]);
}

// ---------------------------------------------------------------------------
// tf32 mma.sync GEMM. For the QKV instance (vb != nullptr), rows >= 512
// (the V channels) are ALSO written as bf16 to vtb[bh][d][j] in the epilogue,
// replacing the separate convert_v kernel.
// ---------------------------------------------------------------------------
#define APITCH 36
template<bool RES>
__global__ __launch_bounds__(256)
void gemm_mma(const float* __restrict__ W, const float* __restrict__ Bm,
              const float* __restrict__ bias, const float* __restrict__ resid,
              float* __restrict__ out, int M, __nv_bfloat16* __restrict__ vb)
{
    extern __shared__ float sm[];
    float (*As)[128][APITCH] = (float(*)[128][APITCH])sm;
    float (*Bs)[128][APITCH] = (float(*)[128][APITCH])(sm + 2 * 128 * APITCH);

    const int b    = blockIdx.z;
    const int o0   = blockIdx.y * 128;
    const int l0   = blockIdx.x * 128;
    const int t    = threadIdx.x;
    const int wid  = t >> 5, lane = t & 31;
    const int wm   = (wid & 1) * 64;
    const int wn   = (wid >> 1) * 32;
    const int lr   = lane >> 2;
    const int lc   = lane & 3;

    const float* Wp = W  + (size_t)o0 * CDIM;
    const float* Bp = Bm + (size_t)b * LDIM * CDIM + (size_t)l0 * CDIM;

    const uint32_t asm_b = s2u(sm);
    const uint32_t bsm_b = asm_b + 2u * 128u * APITCH * 4u;

    auto load_chunk = [&](int c, int st) {
        const uint32_t stoff = (uint32_t)st * 128u * APITCH * 4u;
#pragma unroll
        for (int r = 0; r < 4; ++r) {
            const int idx = r * 256 + t;
            const int row = idx >> 3;
            const int c4  = (idx & 7) * 4;
            const uint32_t so = stoff + (uint32_t)(row * APITCH + c4) * 4u;
            cp16(asm_b + so, Wp + (size_t)row * CDIM + c * 32 + c4);
            cp16(bsm_b + so, Bp + (size_t)row * CDIM + c * 32 + c4);
        }
    };

    float acc[4][4][4];
#pragma unroll
    for (int i = 0; i < 4; ++i)
#pragma unroll
        for (int j = 0; j < 4; ++j)
#pragma unroll
            for (int k = 0; k < 4; ++k) acc[i][j][k] = 0.f;

    load_chunk(0, 0);
    cp_commit();

    for (int c = 0; c < 8; ++c) {
        if (c + 1 < 8) load_chunk(c + 1, (c + 1) & 1);
        cp_commit();
        cp_wait<1>();
        __syncthreads();
        const int st = c & 1;

#pragma unroll
        for (int ks = 0; ks < 4; ++ks) {
            const int kc = ks * 8 + lc;
            uint32_t af[4][4];
#pragma unroll
            for (int mf = 0; mf < 4; ++mf) {
                const int r0 = wm + mf * 16 + lr;
                af[mf][0] = __float_as_uint(As[st][r0][kc]);
                af[mf][1] = __float_as_uint(As[st][r0 + 8][kc]);
                af[mf][2] = __float_as_uint(As[st][r0][kc + 4]);
                af[mf][3] = __float_as_uint(As[st][r0 + 8][kc + 4]);
            }
            uint32_t bf[4][2];
#pragma unroll
            for (int nf = 0; nf < 4; ++nf) {
                const int n = wn + nf * 8 + lr;
                bf[nf][0] = __float_as_uint(Bs[st][n][kc]);
                bf[nf][1] = __float_as_uint(Bs[st][n][kc + 4]);
            }
#pragma unroll
            for (int mf = 0; mf < 4; ++mf)
#pragma unroll
                for (int nf = 0; nf < 4; ++nf)
                    mma_tf32(acc[mf][nf], af[mf], bf[nf]);
        }
        __syncthreads();
    }

#pragma unroll
    for (int mf = 0; mf < 4; ++mf) {
        const int r0 = o0 + wm + mf * 16 + lr;
        const float b0 = __ldg(&bias[r0]);
        const float b1 = __ldg(&bias[r0 + 8]);
        const size_t ro0 = ((size_t)b * M + r0) * LDIM;
        const size_t ro1 = ((size_t)b * M + r0 + 8) * LDIM;
#pragma unroll
        for (int nf = 0; nf < 4; ++nf) {
            const int cc = l0 + wn + nf * 8 + 2 * lc;
            float2 v0 = make_float2(acc[mf][nf][0] + b0, acc[mf][nf][1] + b0);
            float2 v1 = make_float2(acc[mf][nf][2] + b1, acc[mf][nf][3] + b1);
            if (RES) {
                float2 x0 = *(const float2*)&resid[ro0 + cc];
                float2 x1 = *(const float2*)&resid[ro1 + cc];
                v0.x += x0.x; v0.y += x0.y; v1.x += x1.x; v1.y += x1.y;
            }
            *(float2*)&out[ro0 + cc] = v0;
            *(float2*)&out[ro1 + cc] = v1;
            // fused V bf16 cast for the QKV instance (rows 512..767)
            if (vb != nullptr && r0 >= 512) {
                const int dl0 = r0 - 512;           // 0..255: h = dl0>>5, d = dl0&31
                const int dl1 = dl0 + 8;            // same h (d in 0..7 or 16..23)
                const size_t vo0 = ((size_t)(b * 8 + (dl0 >> 5)) * 32 + (dl0 & 31)) * LDIM + cc;
                const size_t vo1 = ((size_t)(b * 8 + (dl1 >> 5)) * 32 + (dl1 & 31)) * LDIM + cc;
                *(uint32_t*)&vb[vo0] = bf2(v0.x, v0.y);
                *(uint32_t*)&vb[vo1] = bf2(v1.x, v1.y);
            }
        }
    }
}

// ---------------------------------------------------------------------------
// Flash attention v4: bf16 m16n8k16 with P KEPT IN REGISTERS.
// QK C-fragment layout == PV A-fragment layout (m16n8 C -> m16n8k16 A with
// adjacent n-blocks paired as k16 halves), so exp'd probs are packed straight
// into A-frags: no P smem, no STS, no syncwarp, no P-ldsm.
// Per iter/warp: 8 ldsm.x4 + 32 k16 MMAs + 32 ex2 + 16 cvt. smem 10KB.
// ---------------------------------------------------------------------------
#define TPB 40
__global__ __launch_bounds__(64, 8)
void attn_mma(const float* __restrict__ qkv, const __nv_bfloat16* __restrict__ kt,
              const __nv_bfloat16* __restrict__ vt, float* __restrict__ attnout)
{
    __shared__ __align__(16) __nv_bfloat16 KS[2][32][TPB];   // [st][j][d]
    __shared__ __align__(16) __nv_bfloat16 VS[2][32][TPB];   // [st][d][j]

    const int bh   = blockIdx.x;
    const int b    = bh >> 3;
    const int h    = bh & 7;
    const int qt   = blockIdx.y;
    const int t    = threadIdx.x;
    const int wid  = t >> 5, lane = t & 31;
    const int lr   = lane >> 2;   // 0..7
    const int lc   = lane & 3;    // 0..3
    const int mi   = lane >> 3;   // ldsm matrix index 0..3
    const int mr   = lane & 7;    // ldsm row within matrix

    const float* Qp = qkv + (size_t)(b * 768 + h * 32) * LDIM;
    const __nv_bfloat16* Ktp = kt + (size_t)bh * LDIM * 32;
    const __nv_bfloat16* Vtp = vt + (size_t)bh * 32 * LDIM;

    const float S = 0.17677669529663687f * 1.4426950408889634f;  // dh^-0.5 * log2e

    const int i0 = qt * 64 + wid * 32;

    // Q fragments bf16, persistent: qf[rh][kstep][4]
    uint32_t qf[2][2][4];
#pragma unroll
    for (int rh = 0; rh < 2; ++rh) {
        const int iq = i0 + rh * 16;
#pragma unroll
        for (int ks = 0; ks < 2; ++ks) {
            const int d0 = 16 * ks + 2 * lc;
            const float qa = Qp[(size_t)d0 * LDIM + iq + lr] * S;
            const float qb = Qp[(size_t)(d0 + 1) * LDIM + iq + lr] * S;
            const float qc = Qp[(size_t)d0 * LDIM + iq + lr + 8] * S;
            const float qd = Qp[(size_t)(d0 + 1) * LDIM + iq + lr + 8] * S;
            const float qe = Qp[(size_t)(d0 + 8) * LDIM + iq + lr] * S;
            const float qg = Qp[(size_t)(d0 + 9) * LDIM + iq + lr] * S;
            const float qh = Qp[(size_t)(d0 + 8) * LDIM + iq + lr + 8] * S;
            const float qi = Qp[(size_t)(d0 + 9) * LDIM + iq + lr + 8] * S;
            qf[rh][ks][0] = bf2(qa, qb);
            qf[rh][ks][1] = bf2(qc, qd);
            qf[rh][ks][2] = bf2(qe, qg);
            qf[rh][ks][3] = bf2(qh, qi);
        }
    }

    float o[2][4][4];
#pragma unroll
    for (int rh = 0; rh < 2; ++rh)
#pragma unroll
        for (int i = 0; i < 4; ++i)
#pragma unroll
            for (int j = 0; j < 4; ++j) o[rh][i][j] = 0.f;
    float rsA[2] = {0.f, 0.f}, rsB[2] = {0.f, 0.f};

    const uint32_t ks_u[2] = { s2u(&KS[0][0][0]), s2u(&KS[1][0][0]) };
    const uint32_t vs_u[2] = { s2u(&VS[0][0][0]), s2u(&VS[1][0][0]) };

    // tile copier: K 32x32 + V 32x32 bf16; 64 threads x (2 K + 2 V) chunks
    auto copy_tile = [&](int st, int j0) {
#pragma unroll
        for (int r = 0; r < 2; ++r) {
            const int idx = r * 64 + t;          // 0..127
            const int row = idx >> 2;            // 0..31
            const int ch  = (idx & 3) * 8;       // bf16 elems 0,8,16,24
            cp16(ks_u[st] + (uint32_t)(row * TPB + ch) * 2u,
                 Ktp + (size_t)(j0 + row) * 32 + ch);
            cp16(vs_u[st] + (uint32_t)(row * TPB + ch) * 2u,
                 Vtp + (size_t)row * LDIM + j0 + ch);
        }
    };

    copy_tile(0, 0);
    cp_commit();

    for (int jt = 0; jt < 32; ++jt) {
        const int st = jt & 1;
        if (jt < 31) copy_tile(st ^ 1, (jt + 1) * 32);
        cp_commit();
        cp_wait<1>();
        __syncthreads();

        // ---- QK: c[rh][g] over 32 keys; K B-frags shared across row-halves ----
        float c[2][4][4];
#pragma unroll
        for (int rh = 0; rh < 2; ++rh)
#pragma unroll
            for (int g = 0; g < 4; ++g)
#pragma unroll
                for (int k = 0; k < 4; ++k) c[rh][g][k] = 0.f;

#pragma unroll
        for (int g = 0; g < 4; ++g) {
            uint32_t r0, r1, r2, r3;
            ldsm4(r0, r1, r2, r3,
                  ks_u[st] + (uint32_t)(((g * 8 + mr) * TPB + mi * 8) * 2));
            uint32_t b01[2] = { r0, r1 }, b23[2] = { r2, r3 };
            mma_bf16(c[0][g], qf[0][0], b01);
            mma_bf16(c[0][g], qf[0][1], b23);
            mma_bf16(c[1][g], qf[1][0], b01);
            mma_bf16(c[1][g], qf[1][1], b23);
        }

        // ---- exp2 + row sums + pack P straight into PV A-fragments ----
        uint32_t A[2][2][4];   // [rh][kp]; kp pairs g=2kp (k lo8) with g=2kp+1 (k hi8)
#pragma unroll
        for (int rh = 0; rh < 2; ++rh) {
#pragma unroll
            for (int g = 0; g < 4; ++g) {
                const float p0 = ex2(c[rh][g][0]), p1 = ex2(c[rh][g][1]);
                const float p2 = ex2(c[rh][g][2]), p3 = ex2(c[rh][g][3]);
                rsA[rh] += p0 + p1;
                rsB[rh] += p2 + p3;
                const int kp = g >> 1;
                if ((g & 1) == 0) {
                    A[rh][kp][0] = bf2(p0, p1);   // (lr,   k=2lc..+1)
                    A[rh][kp][1] = bf2(p2, p3);   // (lr+8, k=2lc..+1)
                } else {
                    A[rh][kp][2] = bf2(p0, p1);   // (lr,   k=2lc+8..+9)
                    A[rh][kp][3] = bf2(p2, p3);   // (lr+8, k=2lc+8..+9)
                }
            }
        }

        // ---- PV: o[rh][nf] += P * V; V B-frags shared across row-halves ----
#pragma unroll
        for (int nf = 0; nf < 4; ++nf) {
            uint32_t v0, v1, v2, v3;
            ldsm4(v0, v1, v2, v3,
                  vs_u[st] + (uint32_t)(((nf * 8 + mr) * TPB + mi * 8) * 2));
            uint32_t b01[2] = { v0, v1 }, b23[2] = { v2, v3 };
            mma_bf16(o[0][nf], A[0][0], b01);
            mma_bf16(o[0][nf], A[0][1], b23);
            mma_bf16(o[1][nf], A[1][0], b01);
            mma_bf16(o[1][nf], A[1][1], b23);
        }
        __syncthreads();
    }

    // quad-reduce row sums, normalize, write [b][l][c]
#pragma unroll
    for (int rh = 0; rh < 2; ++rh) {
        float r0 = rsA[rh], r1 = rsB[rh];
        r0 += __shfl_xor_sync(0xFFFFFFFFu, r0, 1);
        r0 += __shfl_xor_sync(0xFFFFFFFFu, r0, 2);
        r1 += __shfl_xor_sync(0xFFFFFFFFu, r1, 1);
        r1 += __shfl_xor_sync(0xFFFFFFFFu, r1, 2);
        const float inv0 = 1.f / r0;
        const float inv1 = 1.f / r1;
        const int iq = i0 + rh * 16;
#pragma unroll
        for (int nf = 0; nf < 4; ++nf) {
            const int col = h * 32 + 8 * nf + 2 * lc;
            const size_t w0 = ((size_t)b * LDIM + iq + lr) * CDIM + col;
            const size_t w1 = ((size_t)b * LDIM + iq + lr + 8) * CDIM + col;
            *(float2*)&attnout[w0] = make_float2(o[rh][nf][0] * inv0, o[rh][nf][1] * inv0);
            *(float2*)&attnout[w1] = make_float2(o[rh][nf][2] * inv1, o[rh][nf][3] * inv1);
        }
    }
}

// ---------------------------------------------------------------------------
extern "C" void kernel_launch(void* const* d_in, const int* in_sizes, int n_in,
                              void* d_out, int out_size)
{
    const float* x      = (const float*)d_in[0];
    const float* w_qkv  = (const float*)d_in[1];
    const float* b_qkv  = (const float*)d_in[2];
    const float* w_proj = (const float*)d_in[3];
    const float* b_proj = (const float*)d_in[4];
    float* out = (float*)d_out;

    float *qkv = nullptr, *attn = nullptr, *xt = nullptr;
    __nv_bfloat16 *ktb = nullptr, *vtb = nullptr;
    cudaGetSymbolAddress((void**)&qkv, g_qkv);
    cudaGetSymbolAddress((void**)&attn, g_attn);
    cudaGetSymbolAddress((void**)&xt, g_xt);
    cudaGetSymbolAddress((void**)&ktb, g_ktb);
    cudaGetSymbolAddress((void**)&vtb, g_vtb);

    const int SMEMSZ = 4 * 128 * APITCH * 4;
    cudaFuncSetAttribute(gemm_mma<false>, cudaFuncAttributeMaxDynamicSharedMemorySize, SMEMSZ);
    cudaFuncSetAttribute(gemm_mma<true>,  cudaFuncAttributeMaxDynamicSharedMemorySize, SMEMSZ);

    // 1) transpose x -> xt[b][l][c]
    transpose_cl<<<dim3(LDIM / 32, CDIM / 32, BATCH), dim3(32, 8)>>>(x, xt);
    // 2) QKV GEMM (tf32 mma.sync), fused V bf16 cast into vtb[bh][d][j]
    gemm_mma<false><<<dim3(LDIM / 128, 768 / 128, BATCH), 256, SMEMSZ>>>(w_qkv, xt, b_qkv, nullptr, qkv, 768, vtb);
    // 3) K transpose+cast -> ktb[bh][j][d]
    transpose_k<<<dim3(LDIM / 32, BATCH * 8), dim3(32, 8)>>>(qkv, ktb);
    // 4) flash attention v4 (bf16 m16n8k16, P in registers)
    attn_mma<<<dim3(64, LDIM / 64), 64>>>(qkv, ktb, vtb, attn);
    // 5) proj GEMM (tf32) + bias + residual
    gemm_mma<true><<<dim3(LDIM / 128, 256 / 128, BATCH), 256, SMEMSZ>>>(w_proj, attn, b_proj, x, out, 256, nullptr);
}